// round 1
// baseline (speedup 1.0000x reference)
#include <cuda_runtime.h>

#define SEQ   256
#define BATCH 64
#define EMBD  512
#define HID   1024
#define GATE  (4*HID)      // 4096
#define VOCAB 128
#define NCTA  128
#define NTHR  128
#define BH    (BATCH*HID)  // 65536

// -------- persistent scratch (static device globals; no runtime allocs) ------
__device__ float g_XW[(size_t)SEQ * BATCH * GATE];   // 256 MB: per-step input-proj gates
__device__ float g_ys0[(size_t)SEQ * BH];            // 64 MB: layer-0 outputs (all steps)
__device__ float g_h1[2 * BH];                       // layer-1 h double buffer
__device__ unsigned g_barGen;                        // grid barrier generation (monotonic)
__device__ unsigned g_barCnt;                        // grid barrier arrival counter

// -------- grid-wide barrier (all 128 CTAs co-resident: 128 <= 148 SMs) -------
__device__ __forceinline__ void gridbar(unsigned &gen) {
    __syncthreads();
    if (threadIdx.x == 0) {
        const unsigned target = gen + 1u;
        __threadfence();                               // release our writes
        unsigned arrived = atomicAdd(&g_barCnt, 1u);
        if (arrived == (unsigned)(gridDim.x - 1)) {
            g_barCnt = 0u;
            __threadfence();
            atomicExch(&g_barGen, target);
        } else {
            while ((int)(*((volatile unsigned *)&g_barGen) - target) < 0) { }
        }
        __threadfence();                               // acquire others' writes
    }
    gen++;
    __syncthreads();
}

// -------- big input-projection GEMM --------------------------------------
// C[m][n] = sum_k A(m,k) * W[n][k] + bias[n],  m < SEQ*BATCH, n < GATE.
// A(m,k) = emb[x[m]][k]  (phase A, xidx != nullptr)  or  Adir[m*Kdim+k].
// Tile 64x64, K-tile 32, 128 threads, 4x8 micro-tile per thread.
__device__ void gemm_phase(const int *xidx, const float *embt, const float *Adir,
                           int Kdim, const float *W, const float *bias,
                           float *C, float *sm)
{
    const int tid = threadIdx.x;
    float *As = sm;               // [64][36]
    float *Bs = sm + 64 * 36;     // [64][36]
    const int numTiles = (SEQ * BATCH / 64) * (GATE / 64);   // 256*64 = 16384

    for (int tile = blockIdx.x; tile < numTiles; tile += NCTA) {
        const int mt = tile >> 6;      // 0..255
        const int nt = tile & 63;      // 0..63
        float acc[4][8];
#pragma unroll
        for (int rr = 0; rr < 4; rr++)
#pragma unroll
            for (int nn = 0; nn < 8; nn++) acc[rr][nn] = 0.f;

        for (int k0 = 0; k0 < Kdim; k0 += 32) {
            __syncthreads();
            // stage A (64x32) and B (64x32) as float4: 512 float4 each / 128 thr
#pragma unroll
            for (int i = 0; i < 4; i++) {
                int idx = tid + i * NTHR;          // 0..511
                int r = idx >> 3, k4 = idx & 7;    // row, float4-col
                int m = mt * 64 + r;
                float4 av;
                if (xidx) {
                    av = *(const float4 *)&embt[(size_t)xidx[m] * EMBD + k0 + 4 * k4];
                } else {
                    av = *(const float4 *)&Adir[(size_t)m * Kdim + k0 + 4 * k4];
                }
                *(float4 *)&As[r * 36 + 4 * k4] = av;
                int n = nt * 64 + r;
                *(float4 *)&Bs[r * 36 + 4 * k4] =
                    *(const float4 *)&W[(size_t)n * Kdim + k0 + 4 * k4];
            }
            __syncthreads();
#pragma unroll
            for (int kk = 0; kk < 8; kk++) {
                float4 a[4], b[8];
#pragma unroll
                for (int rr = 0; rr < 4; rr++)
                    a[rr] = *(const float4 *)&As[((tid >> 3) + 16 * rr) * 36 + kk * 4];
#pragma unroll
                for (int nn = 0; nn < 8; nn++)
                    b[nn] = *(const float4 *)&Bs[((tid & 7) + 8 * nn) * 36 + kk * 4];
#pragma unroll
                for (int rr = 0; rr < 4; rr++)
#pragma unroll
                    for (int nn = 0; nn < 8; nn++)
                        acc[rr][nn] += a[rr].x * b[nn].x + a[rr].y * b[nn].y +
                                       a[rr].z * b[nn].z + a[rr].w * b[nn].w;
            }
        }
        // write back (+bias)
#pragma unroll
        for (int rr = 0; rr < 4; rr++) {
            int m = mt * 64 + (tid >> 3) + 16 * rr;
#pragma unroll
            for (int nn = 0; nn < 8; nn++) {
                int n = nt * 64 + (tid & 7) + 8 * nn;
                C[(size_t)m * GATE + n] = acc[rr][nn] + bias[n];
            }
        }
    }
}

// -------- LSTM recurrence for one layer ----------------------------------
// CTA owns hidden units [u0, u0+8) -> 32 gate rows of Whh cached in smem.
// Per step: gates[64][32] = XW[t] + h_prev @ Whh_sliceT, then pointwise update.
__device__ void lstm_layer(const float *xw, const float *h0L, const float *c0L,
                           const float *Whh, int layer,
                           float *outH, float *outC, float *sm, unsigned &gen)
{
    const int tid = threadIdx.x;
    const int u0 = blockIdx.x * 8;
    float *Ws = sm;                      // [32][1028]
    float *Hs = sm + 32 * 1028;          // [64][132]
    float *Gs = Hs + 64 * 132;           // [64][32]

    // load Whh slice (32 rows x 1024) as float4: 8192 float4 / 128 thr
#pragma unroll 4
    for (int i = 0; i < 64; i++) {
        int idx = tid + i * NTHR;            // 0..8191
        int j = idx >> 8, k4 = idx & 255;    // gate-row j, float4 col
        int r = (j >> 3) * HID + u0 + (j & 7);
        *(float4 *)&Ws[j * 1028 + 4 * k4] =
            *(const float4 *)&Whh[(size_t)r * HID + 4 * k4];
    }
    // c state in registers: pair p = tid + 128*i -> (b=p/8, u=p%8)
    float creg[4];
#pragma unroll
    for (int i = 0; i < 4; i++) {
        int p = tid + i * NTHR;
        int b = p >> 3, u = p & 7;
        creg[i] = c0L[b * HID + u0 + u];
    }
    __syncthreads();

    for (int t = 0; t < SEQ; t++) {
        const float *src;
        float *dst;
        if (layer == 0) {
            src = t ? (g_ys0 + (size_t)(t - 1) * BH) : h0L;
            dst = g_ys0 + (size_t)t * BH;
        } else {
            src = t ? (g_h1 + (size_t)((t - 1) & 1) * BH) : h0L;
            dst = g_h1 + (size_t)(t & 1) * BH;
        }

        // init gate accumulators from precomputed XW (bias already folded in)
        float acc[4][4];
        const float *xwt = xw + (size_t)t * BATCH * GATE;
#pragma unroll
        for (int bb = 0; bb < 4; bb++) {
            int b = (tid >> 3) + 16 * bb;
#pragma unroll
            for (int jj = 0; jj < 4; jj++)
                acc[bb][jj] = xwt[(size_t)b * GATE + jj * HID + u0 + (tid & 7)];
        }

        for (int k0 = 0; k0 < HID; k0 += 128) {
            __syncthreads();
            // stage h tile [64][128] as float4: 2048 float4 / 128 thr
#pragma unroll 4
            for (int i = 0; i < 16; i++) {
                int idx = tid + i * NTHR;        // 0..2047
                int b = idx >> 5, k4 = idx & 31;
                *(float4 *)&Hs[b * 132 + 4 * k4] =
                    *(const float4 *)&src[b * HID + k0 + 4 * k4];
            }
            __syncthreads();
#pragma unroll 2
            for (int kk = 0; kk < 32; kk++) {
                float4 hv[4], wv[4];
#pragma unroll
                for (int bb = 0; bb < 4; bb++)
                    hv[bb] = *(const float4 *)&Hs[((tid >> 3) + 16 * bb) * 132 + kk * 4];
#pragma unroll
                for (int jj = 0; jj < 4; jj++)
                    wv[jj] = *(const float4 *)&Ws[((tid & 7) + 8 * jj) * 1028 + k0 + kk * 4];
#pragma unroll
                for (int bb = 0; bb < 4; bb++)
#pragma unroll
                    for (int jj = 0; jj < 4; jj++)
                        acc[bb][jj] += hv[bb].x * wv[jj].x + hv[bb].y * wv[jj].y +
                                       hv[bb].z * wv[jj].z + hv[bb].w * wv[jj].w;
            }
        }
        // gates -> smem for pointwise stage
#pragma unroll
        for (int bb = 0; bb < 4; bb++) {
            int b = (tid >> 3) + 16 * bb;
#pragma unroll
            for (int jj = 0; jj < 4; jj++)
                Gs[b * 32 + (tid & 7) + 8 * jj] = acc[bb][jj];
        }
        __syncthreads();
        // pointwise LSTM cell update; thread owns same 4 (b,u) pairs every step
#pragma unroll
        for (int i = 0; i < 4; i++) {
            int p = tid + i * NTHR;
            int b = p >> 3, u = p & 7;
            float ig = Gs[b * 32 + u];
            float fg = Gs[b * 32 + 8 + u];
            float gg = Gs[b * 32 + 16 + u];
            float og = Gs[b * 32 + 24 + u];
            ig = 1.f / (1.f + __expf(-ig));
            fg = 1.f / (1.f + __expf(-fg));
            og = 1.f / (1.f + __expf(-og));
            gg = tanhf(gg);
            float c = fg * creg[i] + ig * gg;
            creg[i] = c;
            float h = og * tanhf(c);
            dst[b * HID + u0 + u] = h;
            if (t == SEQ - 1) {
                outH[b * HID + u0 + u] = h;
                outC[b * HID + u0 + u] = c;
            }
        }
        gridbar(gen);   // all CTAs must see new h before next step
    }
}

// -------- final FC: logits[64][128] = h_last @ WfcT + bfc ------------------
__device__ void fc_phase(const float *hlast, const float *Wfc, const float *bfc,
                         float *out)
{
    const int v = blockIdx.x;          // 128 CTAs == VOCAB
    const int tid = threadIdx.x;
    if (tid < BATCH) {
        float s = 0.f;
#pragma unroll 4
        for (int k = 0; k < HID; k += 4) {
            float4 hh = *(const float4 *)&hlast[tid * HID + k];
            float4 ww = *(const float4 *)&Wfc[(size_t)v * HID + k];
            s += hh.x * ww.x + hh.y * ww.y + hh.z * ww.z + hh.w * ww.w;
        }
        out[tid * VOCAB + v] = s + bfc[v];
    }
}

// -------- the single persistent kernel ------------------------------------
__global__ void __launch_bounds__(NTHR, 1) lstm_all_kernel(
    const int *x, const float *h0, const float *c0, const float *embt,
    const float *Wih0, const float *Whh0, const float *b0,
    const float *Wih1, const float *Whh1, const float *b1,
    const float *Wfc, const float *bfc, float *out)
{
    extern __shared__ float sm[];
    unsigned gen = *((volatile unsigned *)&g_barGen);   // stable until 1st barrier

    // Phase A: XW0 = emb[x] @ Wih0^T + b0
    gemm_phase(x, embt, nullptr, EMBD, Wih0, b0, g_XW, sm);
    gridbar(gen);

    // Layer 0 recurrence (writes all ys0; finals -> d_out)
    lstm_layer(g_XW, h0, c0, Whh0, 0,
               out + VOCAB * BATCH,                 // h layer 0
               out + VOCAB * BATCH + 2 * BH,        // c layer 0
               sm, gen);

    // Phase B: XW1 = ys0 @ Wih1^T + b1  (overwrites g_XW)
    gemm_phase(nullptr, nullptr, g_ys0, HID, Wih1, b1, g_XW, sm);
    gridbar(gen);

    // Layer 1 recurrence
    lstm_layer(g_XW, h0 + BH, c0 + BH, Whh1, 1,
               out + VOCAB * BATCH + BH,            // h layer 1
               out + VOCAB * BATCH + 2 * BH + BH,   // c layer 1
               sm, gen);

    // FC head (h_last for t=255 lives in g_h1 buffer 1)
    fc_phase(g_h1 + BH, Wfc, bfc, out);
}

extern "C" void kernel_launch(void *const *d_in, const int *in_sizes, int n_in,
                              void *d_out, int out_size)
{
    const int   *x    = (const int *)d_in[0];
    const float *h0   = (const float *)d_in[1];
    const float *c0   = (const float *)d_in[2];
    const float *embt = (const float *)d_in[3];
    const float *Wih0 = (const float *)d_in[4];
    const float *Whh0 = (const float *)d_in[5];
    const float *b0   = (const float *)d_in[6];
    const float *Wih1 = (const float *)d_in[7];
    const float *Whh1 = (const float *)d_in[8];
    const float *b1   = (const float *)d_in[9];
    const float *Wfc  = (const float *)d_in[10];
    const float *bfc  = (const float *)d_in[11];
    float *out = (float *)d_out;

    // recurrence smem: 32*1028 + 64*132 + 64*32 floats = 173,568 B
    const int smemBytes = (32 * 1028 + 64 * 132 + 64 * 32) * (int)sizeof(float);
    cudaFuncSetAttribute(lstm_all_kernel,
                         cudaFuncAttributeMaxDynamicSharedMemorySize, smemBytes);
    lstm_all_kernel<<<NCTA, NTHR, smemBytes>>>(x, h0, c0, embt, Wih0, Whh0, b0,
                                               Wih1, Whh1, b1, Wfc, bfc, out);
}

// round 2
// speedup vs baseline: 1.0007x; 1.0007x over previous
#include <cuda_runtime.h>

#define SEQ   256
#define BATCH 64
#define EMBD  512
#define HID   1024
#define GATE  (4*HID)      // 4096
#define VOCAB 128
#define NCTA  128
#define NTHR  128
#define BH    (BATCH*HID)  // 65536

// -------- persistent scratch (static device globals; no runtime allocs) ------
__device__ float g_XW[(size_t)SEQ * BATCH * GATE];   // 256 MB: per-step input-proj gates
__device__ float g_ys0[(size_t)SEQ * BH];            // 64 MB: layer-0 outputs (all steps)
__device__ float g_h1[2 * BH];                       // layer-1 h double buffer
__device__ unsigned g_barGen;                        // grid barrier generation (monotonic)
__device__ unsigned g_barCnt;                        // grid barrier arrival counter

// -------- grid-wide barrier (all 128 CTAs co-resident: 128 <= 148 SMs) -------
__device__ __forceinline__ void gridbar(unsigned &gen) {
    __syncthreads();
    if (threadIdx.x == 0) {
        const unsigned target = gen + 1u;
        __threadfence();                               // release our writes
        unsigned arrived = atomicAdd(&g_barCnt, 1u);
        if (arrived == (unsigned)(gridDim.x - 1)) {
            g_barCnt = 0u;
            __threadfence();
            atomicExch(&g_barGen, target);
        } else {
            while ((int)(*((volatile unsigned *)&g_barGen) - target) < 0) { }
        }
        __threadfence();                               // acquire others' writes
    }
    gen++;
    __syncthreads();
}

// -------- big input-projection GEMM --------------------------------------
// C[m][n] = sum_k A(m,k) * W[n][k] + bias[n],  m < SEQ*BATCH, n < GATE.
// A(m,k) = emb[x[m]][k]  (phase A, xidx != nullptr)  or  Adir[m*Kdim+k].
// Tile 64x64, K-tile 32, 128 threads, 4x8 micro-tile per thread.
__device__ void gemm_phase(const int *xidx, const float *embt, const float *Adir,
                           int Kdim, const float *W, const float *bias,
                           float *C, float *sm)
{
    const int tid = threadIdx.x;
    float *As = sm;               // [64][36]
    float *Bs = sm + 64 * 36;     // [64][36]
    const int numTiles = (SEQ * BATCH / 64) * (GATE / 64);   // 256*64 = 16384

    for (int tile = blockIdx.x; tile < numTiles; tile += NCTA) {
        const int mt = tile >> 6;      // 0..255
        const int nt = tile & 63;      // 0..63
        float acc[4][8];
#pragma unroll
        for (int rr = 0; rr < 4; rr++)
#pragma unroll
            for (int nn = 0; nn < 8; nn++) acc[rr][nn] = 0.f;

        for (int k0 = 0; k0 < Kdim; k0 += 32) {
            __syncthreads();
            // stage A (64x32) and B (64x32) as float4: 512 float4 each / 128 thr
#pragma unroll
            for (int i = 0; i < 4; i++) {
                int idx = tid + i * NTHR;          // 0..511
                int r = idx >> 3, k4 = idx & 7;    // row, float4-col
                int m = mt * 64 + r;
                float4 av;
                if (xidx) {
                    av = *(const float4 *)&embt[(size_t)xidx[m] * EMBD + k0 + 4 * k4];
                } else {
                    av = *(const float4 *)&Adir[(size_t)m * Kdim + k0 + 4 * k4];
                }
                *(float4 *)&As[r * 36 + 4 * k4] = av;
                int n = nt * 64 + r;
                *(float4 *)&Bs[r * 36 + 4 * k4] =
                    *(const float4 *)&W[(size_t)n * Kdim + k0 + 4 * k4];
            }
            __syncthreads();
#pragma unroll
            for (int kk = 0; kk < 8; kk++) {
                float4 a[4], b[8];
#pragma unroll
                for (int rr = 0; rr < 4; rr++)
                    a[rr] = *(const float4 *)&As[((tid >> 3) + 16 * rr) * 36 + kk * 4];
#pragma unroll
                for (int nn = 0; nn < 8; nn++)
                    b[nn] = *(const float4 *)&Bs[((tid & 7) + 8 * nn) * 36 + kk * 4];
#pragma unroll
                for (int rr = 0; rr < 4; rr++)
#pragma unroll
                    for (int nn = 0; nn < 8; nn++)
                        acc[rr][nn] += a[rr].x * b[nn].x + a[rr].y * b[nn].y +
                                       a[rr].z * b[nn].z + a[rr].w * b[nn].w;
            }
        }
        // write back (+bias)
#pragma unroll
        for (int rr = 0; rr < 4; rr++) {
            int m = mt * 64 + (tid >> 3) + 16 * rr;
#pragma unroll
            for (int nn = 0; nn < 8; nn++) {
                int n = nt * 64 + (tid & 7) + 8 * nn;
                C[(size_t)m * GATE + n] = acc[rr][nn] + bias[n];
            }
        }
    }
}

// -------- LSTM recurrence for one layer ----------------------------------
// CTA owns hidden units [u0, u0+8) -> 32 gate rows of Whh cached in smem.
// Per step: gates[64][32] = XW[t] + h_prev @ Whh_sliceT, then pointwise update.
__device__ void lstm_layer(const float *xw, const float *h0L, const float *c0L,
                           const float *Whh, int layer,
                           float *outH, float *outC, float *sm, unsigned &gen)
{
    const int tid = threadIdx.x;
    const int u0 = blockIdx.x * 8;
    float *Ws = sm;                      // [32][1028]
    float *Hs = sm + 32 * 1028;          // [64][132]
    float *Gs = Hs + 64 * 132;           // [64][32]

    // load Whh slice (32 rows x 1024) as float4: 8192 float4 / 128 thr
#pragma unroll 4
    for (int i = 0; i < 64; i++) {
        int idx = tid + i * NTHR;            // 0..8191
        int j = idx >> 8, k4 = idx & 255;    // gate-row j, float4 col
        int r = (j >> 3) * HID + u0 + (j & 7);
        *(float4 *)&Ws[j * 1028 + 4 * k4] =
            *(const float4 *)&Whh[(size_t)r * HID + 4 * k4];
    }
    // c state in registers: pair p = tid + 128*i -> (b=p/8, u=p%8)
    float creg[4];
#pragma unroll
    for (int i = 0; i < 4; i++) {
        int p = tid + i * NTHR;
        int b = p >> 3, u = p & 7;
        creg[i] = c0L[b * HID + u0 + u];
    }
    __syncthreads();

    for (int t = 0; t < SEQ; t++) {
        const float *src;
        float *dst;
        if (layer == 0) {
            src = t ? (g_ys0 + (size_t)(t - 1) * BH) : h0L;
            dst = g_ys0 + (size_t)t * BH;
        } else {
            src = t ? (g_h1 + (size_t)((t - 1) & 1) * BH) : h0L;
            dst = g_h1 + (size_t)(t & 1) * BH;
        }

        // init gate accumulators from precomputed XW (bias already folded in)
        float acc[4][4];
        const float *xwt = xw + (size_t)t * BATCH * GATE;
#pragma unroll
        for (int bb = 0; bb < 4; bb++) {
            int b = (tid >> 3) + 16 * bb;
#pragma unroll
            for (int jj = 0; jj < 4; jj++)
                acc[bb][jj] = xwt[(size_t)b * GATE + jj * HID + u0 + (tid & 7)];
        }

        for (int k0 = 0; k0 < HID; k0 += 128) {
            __syncthreads();
            // stage h tile [64][128] as float4: 2048 float4 / 128 thr
#pragma unroll 4
            for (int i = 0; i < 16; i++) {
                int idx = tid + i * NTHR;        // 0..2047
                int b = idx >> 5, k4 = idx & 31;
                *(float4 *)&Hs[b * 132 + 4 * k4] =
                    *(const float4 *)&src[b * HID + k0 + 4 * k4];
            }
            __syncthreads();
#pragma unroll 2
            for (int kk = 0; kk < 32; kk++) {
                float4 hv[4], wv[4];
#pragma unroll
                for (int bb = 0; bb < 4; bb++)
                    hv[bb] = *(const float4 *)&Hs[((tid >> 3) + 16 * bb) * 132 + kk * 4];
#pragma unroll
                for (int jj = 0; jj < 4; jj++)
                    wv[jj] = *(const float4 *)&Ws[((tid & 7) + 8 * jj) * 1028 + k0 + kk * 4];
#pragma unroll
                for (int bb = 0; bb < 4; bb++)
#pragma unroll
                    for (int jj = 0; jj < 4; jj++)
                        acc[bb][jj] += hv[bb].x * wv[jj].x + hv[bb].y * wv[jj].y +
                                       hv[bb].z * wv[jj].z + hv[bb].w * wv[jj].w;
            }
        }
        // gates -> smem for pointwise stage
#pragma unroll
        for (int bb = 0; bb < 4; bb++) {
            int b = (tid >> 3) + 16 * bb;
#pragma unroll
            for (int jj = 0; jj < 4; jj++)
                Gs[b * 32 + (tid & 7) + 8 * jj] = acc[bb][jj];
        }
        __syncthreads();
        // pointwise LSTM cell update; thread owns same 4 (b,u) pairs every step
#pragma unroll
        for (int i = 0; i < 4; i++) {
            int p = tid + i * NTHR;
            int b = p >> 3, u = p & 7;
            float ig = Gs[b * 32 + u];
            float fg = Gs[b * 32 + 8 + u];
            float gg = Gs[b * 32 + 16 + u];
            float og = Gs[b * 32 + 24 + u];
            ig = 1.f / (1.f + __expf(-ig));
            fg = 1.f / (1.f + __expf(-fg));
            og = 1.f / (1.f + __expf(-og));
            gg = tanhf(gg);
            float c = fg * creg[i] + ig * gg;
            creg[i] = c;
            float h = og * tanhf(c);
            dst[b * HID + u0 + u] = h;
            if (t == SEQ - 1) {
                outH[b * HID + u0 + u] = h;
                outC[b * HID + u0 + u] = c;
            }
        }
        gridbar(gen);   // all CTAs must see new h before next step
    }
}

// -------- final FC: logits[64][128] = h_last @ WfcT + bfc ------------------
__device__ void fc_phase(const float *hlast, const float *Wfc, const float *bfc,
                         float *out)
{
    const int v = blockIdx.x;          // 128 CTAs == VOCAB
    const int tid = threadIdx.x;
    if (tid < BATCH) {
        float s = 0.f;
#pragma unroll 4
        for (int k = 0; k < HID; k += 4) {
            float4 hh = *(const float4 *)&hlast[tid * HID + k];
            float4 ww = *(const float4 *)&Wfc[(size_t)v * HID + k];
            s += hh.x * ww.x + hh.y * ww.y + hh.z * ww.z + hh.w * ww.w;
        }
        out[tid * VOCAB + v] = s + bfc[v];
    }
}

// -------- the single persistent kernel ------------------------------------
__global__ void __launch_bounds__(NTHR, 1) lstm_all_kernel(
    const int *x, const float *h0, const float *c0, const float *embt,
    const float *Wih0, const float *Whh0, const float *b0,
    const float *Wih1, const float *Whh1, const float *b1,
    const float *Wfc, const float *bfc, float *out)
{
    extern __shared__ float sm[];
    unsigned gen = *((volatile unsigned *)&g_barGen);   // stable until 1st barrier

    // Phase A: XW0 = emb[x] @ Wih0^T + b0
    gemm_phase(x, embt, nullptr, EMBD, Wih0, b0, g_XW, sm);
    gridbar(gen);

    // Layer 0 recurrence (writes all ys0; finals -> d_out)
    lstm_layer(g_XW, h0, c0, Whh0, 0,
               out + VOCAB * BATCH,                 // h layer 0
               out + VOCAB * BATCH + 2 * BH,        // c layer 0
               sm, gen);

    // Phase B: XW1 = ys0 @ Wih1^T + b1  (overwrites g_XW)
    gemm_phase(nullptr, nullptr, g_ys0, HID, Wih1, b1, g_XW, sm);
    gridbar(gen);

    // Layer 1 recurrence
    lstm_layer(g_XW, h0 + BH, c0 + BH, Whh1, 1,
               out + VOCAB * BATCH + BH,            // h layer 1
               out + VOCAB * BATCH + 2 * BH + BH,   // c layer 1
               sm, gen);

    // FC head (h_last for t=255 lives in g_h1 buffer 1)
    fc_phase(g_h1 + BH, Wfc, bfc, out);
}

extern "C" void kernel_launch(void *const *d_in, const int *in_sizes, int n_in,
                              void *d_out, int out_size)
{
    const int   *x    = (const int *)d_in[0];
    const float *h0   = (const float *)d_in[1];
    const float *c0   = (const float *)d_in[2];
    const float *embt = (const float *)d_in[3];
    const float *Wih0 = (const float *)d_in[4];
    const float *Whh0 = (const float *)d_in[5];
    const float *b0   = (const float *)d_in[6];
    const float *Wih1 = (const float *)d_in[7];
    const float *Whh1 = (const float *)d_in[8];
    const float *b1   = (const float *)d_in[9];
    const float *Wfc  = (const float *)d_in[10];
    const float *bfc  = (const float *)d_in[11];
    float *out = (float *)d_out;

    // recurrence smem: 32*1028 + 64*132 + 64*32 floats = 173,568 B
    const int smemBytes = (32 * 1028 + 64 * 132 + 64 * 32) * (int)sizeof(float);
    cudaFuncSetAttribute(lstm_all_kernel,
                         cudaFuncAttributeMaxDynamicSharedMemorySize, smemBytes);
    lstm_all_kernel<<<NCTA, NTHR, smemBytes>>>(x, h0, c0, embt, Wih0, Whh0, b0,
                                               Wih1, Whh1, b1, Wfc, bfc, out);
}